// round 9
// baseline (speedup 1.0000x reference)
#include <cuda_runtime.h>
#include <cstdint>

// ===========================================================================
// NNUE eval via tensor-core mma.sync (tf32, m16n8k8), compute_103-safe PTX.
// 296 persistent CTAs x 128 threads; tile = 128 samples; warp owns 32 rows
// (m=2).  ~93.4 KB smem/CTA -> 2 CTAs/SM; 256 thr/SM -> 256 regs/thread
// budget (no spills with 64-reg L1 accumulator).
//
// XP region (stride 104/row) is reused three ways per row:
//   [0,64)   raw X cols 0..63  -> overwritten by `base` (64 outs) after L1
//   [64,96)  raw X cols 64..95 -> overwritten by `x0` (32 outs) after L2
//   [96,104) raw cols 96,97 at offsets 96,98 (restaged per tile);
//            pad cols 98..103 zeroed ONCE (never clobbered).
// ===========================================================================

__device__ __forceinline__ uint32_t f2tf32(float f) {
    uint32_t r; asm("cvt.rna.tf32.f32 %0, %1;" : "=r"(r) : "f"(f)); return r;
}

__device__ __forceinline__ void mma8(float* d,
                                     uint32_t a0, uint32_t a1, uint32_t a2, uint32_t a3,
                                     uint32_t b0, uint32_t b1) {
    asm volatile(
        "mma.sync.aligned.m16n8k8.row.col.f32.tf32.tf32.f32 "
        "{%0,%1,%2,%3}, {%4,%5,%6,%7}, {%8,%9}, {%0,%1,%2,%3};"
        : "+f"(d[0]), "+f"(d[1]), "+f"(d[2]), "+f"(d[3])
        : "r"(a0), "r"(a1), "r"(a2), "r"(a3), "r"(b0), "r"(b1));
}

// ---- pre-packed per-lane B fragments (device globals) ---------------------
__device__ uint32_t g_Bf1[13 * 8 * 32 * 2];
__device__ uint32_t g_Bf2[8 * 4 * 32 * 2];
__device__ uint32_t g_Bf3[4 * 4 * 32 * 2];

__global__ void nnue_setup(const float* __restrict__ Ww,
                           const float* __restrict__ Wb,
                           const float* __restrict__ W0,
                           const float* __restrict__ W1) {
    int t = blockIdx.x * blockDim.x + threadIdx.x;
    if (t < 6656) {
        int e = t & 1, lane = (t >> 1) & 31, tn = (t >> 6) & 7, s = t >> 9;
        int n = 8 * tn + (lane >> 2);
        int k = 8 * s + (lane & 3) + 4 * e;
        float v = 0.0f;
        if (k < 98) {
            if (n < 32) v = Ww[n * 98 + k];
            else { int kk = k + 49; if (kk >= 98) kk -= 98; v = Wb[(n - 32) * 98 + kk]; }
        }
        g_Bf1[t] = f2tf32(v);
    }
    if (t < 2048) {
        int e = t & 1, lane = (t >> 1) & 31, tn = (t >> 6) & 3, s = t >> 8;
        int n = 8 * tn + (lane >> 2);
        int k = 8 * s + (lane & 3) + 4 * e;
        g_Bf2[t] = f2tf32(W0[n * 64 + k]);
    }
    if (t < 1024) {
        int e = t & 1, lane = (t >> 1) & 31, tn = (t >> 6) & 3, s = t >> 8;
        int n = 8 * tn + (lane >> 2);
        int k = 8 * s + (lane & 3) + 4 * e;
        g_Bf3[t] = f2tf32(W1[n * 32 + k]);
    }
}

// ---- smem layout (u32 offsets) --------------------------------------------
#define U_XP    0          // 128 rows x 104
#define U_BF1   13312      // 6656
#define U_BF2   19968      // 2048
#define U_BF3   22016      // 1024
#define U_BIAS1 23040      // 64
#define U_B0    23104      // 32
#define U_B1    23136      // 32
#define U_W2    23168      // 64
#define U_POV   23232      // 128
#define U_B2    23360      // 1 (+pad)
#define SMEM_BYTES (23364 * 4)    // ~93.5 KB

// swizzled column offset within a pair-layout row (col 0..103)
__device__ __forceinline__ int coff(int col) {
    return (col & 0xF8) | ((col & 3) << 1) | ((col >> 2) & 1);
}
// x0 slot for col 0..31 within a row: offsets [64,96)
__device__ __forceinline__ int x0off(int col) {
    return 64 + ((col & 24) | ((col & 3) << 1) | ((col >> 2) & 1));
}

__global__ __launch_bounds__(128, 2)
void nnue_mma(const float* __restrict__ pov,
              const float* __restrict__ white,
              const float* __restrict__ black,
              const float* __restrict__ bw,
              const float* __restrict__ bb,
              const float* __restrict__ b0,
              const float* __restrict__ b1,
              const float* __restrict__ W2,
              const float* __restrict__ b2,
              float* __restrict__ out, int ntiles) {
    extern __shared__ __align__(16) uint32_t shu[];
    float* shf = (float*)shu;
    const int t = threadIdx.x;
    const int lane = t & 31, wid = t >> 5;
    const int g = lane >> 2, q = lane & 3;
    const int r0 = wid * 32;

    // ---- one-time: fragments, vectors, pad zeros --------------------------
    {
        uint4* d = (uint4*)(shu + U_BF1); const uint4* s = (const uint4*)g_Bf1;
        for (int i = t; i < 1664; i += 128) d[i] = s[i];
        d = (uint4*)(shu + U_BF2); s = (const uint4*)g_Bf2;
        for (int i = t; i < 512; i += 128) d[i] = s[i];
        d = (uint4*)(shu + U_BF3); s = (const uint4*)g_Bf3;
        for (int i = t; i < 256; i += 128) d[i] = s[i];
    }
    if (t < 64) shf[U_BIAS1 + t] = (t < 32) ? bw[t] : bb[t - 32];
    if (t < 64) shf[U_W2 + t]    = W2[t];
    if (t < 32) shf[U_B0 + t]    = b0[t];
    if (t < 32) shf[U_B1 + t]    = b1[t];
    if (t == 0) shf[U_B2]        = b2[0];
    {   // zero pad cols 98..103 ONCE (slots never clobbered by overlays)
        for (int i = t; i < 768; i += 128) {
            int s = i / 6;
            int c = 98 + (i - s * 6);
            shu[U_XP + s * 104 + coff(c)] = 0;
        }
    }
    __syncthreads();
    const float b2val = shf[U_B2];

    // staging: i = t + 128*j ; each step k += 30, s += 2 (mod 49)
    const int s_init = t / 49;
    const int k_init = t - s_init * 49;

    for (int tile = blockIdx.x; tile < ntiles; tile += gridDim.x) {
        const size_t s0 = (size_t)tile * 128;

        // ---- stage X (tf32, pair layout) + pov ----------------------------
        {
            const float* wp = white + s0 * 49;
            const float* bp = black + s0 * 49;
            int s = s_init, k = k_init;
#pragma unroll 1
            for (int j = 0; j < 49; j++) {
                int i = t + (j << 7);
                float wv = wp[i];
                float bv = bp[i];
                int base = s * 104;
                shu[U_XP + base + coff(k)]      = f2tf32(wv);
                shu[U_XP + base + coff(k + 49)] = f2tf32(bv);
                k += 30; s += 2;
                if (k >= 49) { k -= 49; s += 1; }
            }
        }
        shf[U_POV + t] = pov[s0 + t];
        __syncthreads();

        // ---- layer 1: D1[128x64] = X @ Wc^T, K=104, m=2 -------------------
        float acc1[2][8][4];
#pragma unroll
        for (int m = 0; m < 2; m++)
#pragma unroll
            for (int tn = 0; tn < 8; tn++)
#pragma unroll
                for (int r = 0; r < 4; r++) acc1[m][tn][r] = 0.0f;

#pragma unroll
        for (int s = 0; s < 13; s++) {
            uint2 aa[2][2];
#pragma unroll
            for (int m = 0; m < 2; m++)
#pragma unroll
                for (int h = 0; h < 2; h++)
                    aa[m][h] = *(const uint2*)&shu[U_XP + (r0 + 16 * m + 8 * h + g) * 104
                                                   + (s * 4 + q) * 2];
#pragma unroll
            for (int tn = 0; tn < 8; tn++) {
                uint2 bv = *(const uint2*)&shu[U_BF1 + ((s * 8 + tn) * 32 + lane) * 2];
                mma8(acc1[0][tn], aa[0][0].x, aa[0][1].x, aa[0][0].y, aa[0][1].y, bv.x, bv.y);
                mma8(acc1[1][tn], aa[1][0].x, aa[1][1].x, aa[1][0].y, aa[1][1].y, bv.x, bv.y);
            }
        }
        __syncthreads();   // all raw-XP reads complete before overlays

        // ---- epilogue 1: bias + pov mix + relu -> base (in-place, [0,64)) -
#pragma unroll
        for (int m = 0; m < 2; m++)
#pragma unroll
            for (int h = 0; h < 2; h++) {
                int row = r0 + 16 * m + 8 * h + g;
                float p  = shf[U_POV + row];
                float q1 = 1.0f - p;
#pragma unroll
                for (int tn = 0; tn < 4; tn++)
#pragma unroll
                    for (int c = 0; c < 2; c++) {
                        int col = 8 * tn + 2 * q + c;
                        float lo = acc1[m][tn][2 * h + c]     + shf[U_BIAS1 + col];
                        float hi = acc1[m][tn + 4][2 * h + c] + shf[U_BIAS1 + 32 + col];
                        float v0 = fmaxf(p * lo + q1 * hi, 0.0f);
                        float v1 = fmaxf(p * hi + q1 * lo, 0.0f);
                        shu[U_XP + row * 104 + coff(col)]      = f2tf32(v0);
                        shu[U_XP + row * 104 + coff(col + 32)] = f2tf32(v1);
                    }
            }
        __syncwarp();

        // ---- layer 2: D2[128x32] = base @ W0^T, K=64 ----------------------
        float acc2[2][4][4];
#pragma unroll
        for (int m = 0; m < 2; m++)
#pragma unroll
            for (int tn = 0; tn < 4; tn++)
#pragma unroll
                for (int r = 0; r < 4; r++) acc2[m][tn][r] = 0.0f;

#pragma unroll
        for (int s = 0; s < 8; s++) {
            uint2 aa[2][2];
#pragma unroll
            for (int m = 0; m < 2; m++)
#pragma unroll
                for (int h = 0; h < 2; h++)
                    aa[m][h] = *(const uint2*)&shu[U_XP + (r0 + 16 * m + 8 * h + g) * 104
                                                   + (s * 4 + q) * 2];
#pragma unroll
            for (int tn = 0; tn < 4; tn++) {
                uint2 bv = *(const uint2*)&shu[U_BF2 + ((s * 4 + tn) * 32 + lane) * 2];
                mma8(acc2[0][tn], aa[0][0].x, aa[0][1].x, aa[0][0].y, aa[0][1].y, bv.x, bv.y);
                mma8(acc2[1][tn], aa[1][0].x, aa[1][1].x, aa[1][0].y, aa[1][1].y, bv.x, bv.y);
            }
        }

        // ---- epilogue 2: x0 = relu(D2+b0) -> [64,96); W2[0:32] partial dot
        float dot[2][2] = {{0.0f, 0.0f}, {0.0f, 0.0f}};
#pragma unroll
        for (int m = 0; m < 2; m++)
#pragma unroll
            for (int h = 0; h < 2; h++) {
                int row = r0 + 16 * m + 8 * h + g;
#pragma unroll
                for (int tn = 0; tn < 4; tn++)
#pragma unroll
                    for (int c = 0; c < 2; c++) {
                        int col = 8 * tn + 2 * q + c;
                        float v = fmaxf(acc2[m][tn][2 * h + c] + shf[U_B0 + col], 0.0f);
                        dot[m][h] += v * shf[U_W2 + col];
                        shu[U_XP + row * 104 + x0off(col)] = f2tf32(v);
                    }
            }
        __syncwarp();

        // ---- layer 3: D3[128x32] = x0 @ W1^T, K=32 ------------------------
        float acc3[2][4][4];
#pragma unroll
        for (int m = 0; m < 2; m++)
#pragma unroll
            for (int tn = 0; tn < 4; tn++)
#pragma unroll
                for (int r = 0; r < 4; r++) acc3[m][tn][r] = 0.0f;

#pragma unroll
        for (int s = 0; s < 4; s++) {
            uint2 aa[2][2];
#pragma unroll
            for (int m = 0; m < 2; m++)
#pragma unroll
                for (int h = 0; h < 2; h++)
                    aa[m][h] = *(const uint2*)&shu[U_XP + (r0 + 16 * m + 8 * h + g) * 104
                                                   + 64 + (s * 4 + q) * 2];
#pragma unroll
            for (int tn = 0; tn < 4; tn++) {
                uint2 bv = *(const uint2*)&shu[U_BF3 + ((s * 4 + tn) * 32 + lane) * 2];
                mma8(acc3[0][tn], aa[0][0].x, aa[0][1].x, aa[0][0].y, aa[0][1].y, bv.x, bv.y);
                mma8(acc3[1][tn], aa[1][0].x, aa[1][1].x, aa[1][0].y, aa[1][1].y, bv.x, bv.y);
            }
        }

        // ---- epilogue 3: dot += relu(D3+b1).W2[32:]; reduce; store --------
#pragma unroll
        for (int m = 0; m < 2; m++)
#pragma unroll
            for (int h = 0; h < 2; h++) {
#pragma unroll
                for (int tn = 0; tn < 4; tn++)
#pragma unroll
                    for (int c = 0; c < 2; c++) {
                        int col = 8 * tn + 2 * q + c;
                        float v = fmaxf(acc3[m][tn][2 * h + c] + shf[U_B1 + col], 0.0f);
                        dot[m][h] += v * shf[U_W2 + 32 + col];
                    }
                float d = dot[m][h];
                d += __shfl_xor_sync(0xffffffffu, d, 1);
                d += __shfl_xor_sync(0xffffffffu, d, 2);
                if (q == 0)
                    out[s0 + r0 + 16 * m + 8 * h + g] = d + b2val;
            }
        __syncthreads();   // XP free before next tile's staging
    }
}

// ---------------------------------------------------------------------------
extern "C" void kernel_launch(void* const* d_in, const int* in_sizes, int n_in,
                              void* d_out, int out_size) {
    const float* pov   = (const float*)d_in[0];
    const float* white = (const float*)d_in[1];
    const float* black = (const float*)d_in[2];
    const float* Ww    = (const float*)d_in[3];
    const float* bw    = (const float*)d_in[4];
    const float* Wb    = (const float*)d_in[5];
    const float* bb    = (const float*)d_in[6];
    const float* W0    = (const float*)d_in[7];
    const float* b0    = (const float*)d_in[8];
    const float* W1    = (const float*)d_in[9];
    const float* b1    = (const float*)d_in[10];
    const float* W2    = (const float*)d_in[11];
    const float* b2    = (const float*)d_in[12];

    const int B = in_sizes[0];
    const int ntiles = B / 128;

    cudaFuncSetAttribute(nnue_mma,
                         cudaFuncAttributeMaxDynamicSharedMemorySize, SMEM_BYTES);

    nnue_setup<<<26, 256>>>(Ww, Wb, W0, W1);
    nnue_mma<<<296, 128, SMEM_BYTES>>>(pov, white, black, bw, bb,
                                       b0, b1, W2, b2, (float*)d_out, ntiles);
}

// round 10
// speedup vs baseline: 3.4876x; 3.4876x over previous
#include <cuda_runtime.h>
#include <cstdint>

// ===========================================================================
// NNUE eval via tensor-core mma.sync (tf32, m16n8k8), compute_103-safe PTX.
// 148 persistent CTAs x 256 threads; tile = 256 samples; warp owns 32 rows
// (fully private: stage -> L1 -> mix -> L2 -> L3 -> store, no block barriers).
// Staging is batched float4 LDG (MLP=12) to kill the LDG->STS serial chain
// that dominated R6-R9.
// ===========================================================================

__device__ __forceinline__ uint32_t f2tf32(float f) {
    uint32_t r; asm("cvt.rna.tf32.f32 %0, %1;" : "=r"(r) : "f"(f)); return r;
}

__device__ __forceinline__ void mma8(float* d,
                                     uint32_t a0, uint32_t a1, uint32_t a2, uint32_t a3,
                                     uint32_t b0, uint32_t b1) {
    asm volatile(
        "mma.sync.aligned.m16n8k8.row.col.f32.tf32.tf32.f32 "
        "{%0,%1,%2,%3}, {%4,%5,%6,%7}, {%8,%9}, {%0,%1,%2,%3};"
        : "+f"(d[0]), "+f"(d[1]), "+f"(d[2]), "+f"(d[3])
        : "r"(a0), "r"(a1), "r"(a2), "r"(a3), "r"(b0), "r"(b1));
}

// ---- pre-packed per-lane B fragments (device globals) ---------------------
__device__ uint32_t g_Bf1[13 * 8 * 32 * 2];
__device__ uint32_t g_Bf2[8 * 4 * 32 * 2];
__device__ uint32_t g_Bf3[4 * 4 * 32 * 2];

__global__ void nnue_setup(const float* __restrict__ Ww,
                           const float* __restrict__ Wb,
                           const float* __restrict__ W0,
                           const float* __restrict__ W1) {
    int t = blockIdx.x * blockDim.x + threadIdx.x;
    if (t < 6656) {
        int e = t & 1, lane = (t >> 1) & 31, tn = (t >> 6) & 7, s = t >> 9;
        int n = 8 * tn + (lane >> 2);
        int k = 8 * s + (lane & 3) + 4 * e;
        float v = 0.0f;
        if (k < 98) {
            if (n < 32) v = Ww[n * 98 + k];
            else { int kk = k + 49; if (kk >= 98) kk -= 98; v = Wb[(n - 32) * 98 + kk]; }
        }
        g_Bf1[t] = f2tf32(v);
    }
    if (t < 2048) {
        int e = t & 1, lane = (t >> 1) & 31, tn = (t >> 6) & 3, s = t >> 8;
        int n = 8 * tn + (lane >> 2);
        int k = 8 * s + (lane & 3) + 4 * e;
        g_Bf2[t] = f2tf32(W0[n * 64 + k]);
    }
    if (t < 1024) {
        int e = t & 1, lane = (t >> 1) & 31, tn = (t >> 6) & 3, s = t >> 8;
        int n = 8 * tn + (lane >> 2);
        int k = 8 * s + (lane & 3) + 4 * e;
        g_Bf3[t] = f2tf32(W1[n * 32 + k]);
    }
}

// ---- smem layout (u32 offsets) --------------------------------------------
// XP: 256 rows x stride 104.  Per row: raw X cols (pair-swizzled) in [0,104);
// after L1, base (64) overwrites [0,64); after L2, x0 (32) overwrites [64,96).
// Pad slots {97,99,100,101,102,103} zeroed per tile (base clobbers them via
// nothing — they are only clobbered by next tile's staging; re-zeroed anyway).
// Stride 104 ≡ 8 (mod 32): conflict-free LDS.64 A-fragment loads.
#define U_XP    0
#define U_BF1   26624
#define U_BF2   33280
#define U_BF3   35328
#define U_BIAS1 36352
#define U_B0    36416
#define U_B1    36448
#define U_W2    36480
#define U_B2    36544
#define SMEM_BYTES (36548 * 4)   // ~146 KB -> 1 CTA/SM, 256 regs/thread budget

// swizzled column offset within a pair-layout row (col 0..103)
__device__ __forceinline__ int coff(int col) {
    return (col & 0xF8) | ((col & 3) << 1) | ((col >> 2) & 1);
}

// scatter one float4 pair (white,black) for local sample s, col k..k+3
__device__ __forceinline__ void scatter4(uint32_t* shu, int r0, int s, int k,
                                         float4 w4, float4 b4) {
    float wf[4] = {w4.x, w4.y, w4.z, w4.w};
    float bf[4] = {b4.x, b4.y, b4.z, b4.w};
#pragma unroll
    for (int c = 0; c < 4; c++) {
        int rr = r0 + s, kc = k + c;
        if (kc >= 49) { kc -= 49; rr += 1; }
        int b = rr * 104;
        shu[b + coff(kc)]      = f2tf32(wf[c]);
        shu[b + coff(kc + 49)] = f2tf32(bf[c]);
    }
}

__global__ __launch_bounds__(256, 1)
void nnue_mma(const float* __restrict__ pov,
              const float* __restrict__ white,
              const float* __restrict__ black,
              const float* __restrict__ bw,
              const float* __restrict__ bb,
              const float* __restrict__ b0,
              const float* __restrict__ b1,
              const float* __restrict__ W2,
              const float* __restrict__ b2,
              float* __restrict__ out, int ntiles) {
    extern __shared__ __align__(16) uint32_t shu[];
    float* shf = (float*)shu;
    const int t = threadIdx.x;
    const int lane = t & 31, wid = t >> 5;
    const int g = lane >> 2, q = lane & 3;
    const int r0 = wid * 32;

    // ---- one-time: fragments + vectors ------------------------------------
    {
        uint4* d = (uint4*)(shu + U_BF1); const uint4* s = (const uint4*)g_Bf1;
        for (int i = t; i < 1664; i += 256) d[i] = s[i];
        d = (uint4*)(shu + U_BF2); s = (const uint4*)g_Bf2;
        for (int i = t; i < 512; i += 256) d[i] = s[i];
        d = (uint4*)(shu + U_BF3); s = (const uint4*)g_Bf3;
        for (int i = t; i < 256; i += 256) d[i] = s[i];
    }
    if (t < 64) shf[U_BIAS1 + t] = (t < 32) ? bw[t] : bb[t - 32];
    if (t < 64) shf[U_W2 + t]    = W2[t];
    if (t < 32) shf[U_B0 + t]    = b0[t];
    if (t < 32) shf[U_B1 + t]    = b1[t];
    if (t == 0) shf[U_B2]        = b2[0];
    __syncthreads();            // only block barrier in the kernel
    const float b2val = shf[U_B2];

    // staging decomposition: element i = 4*lane + 128*j over this warp's
    // 32*49 = 1568 floats; 128 = 2*49 + 30.
    const int s_init = (4 * lane) / 49;
    const int k_init = 4 * lane - 49 * s_init;

    for (int tile = blockIdx.x; tile < ntiles; tile += gridDim.x) {
        const size_t s0 = (size_t)tile * 256;
        const float4* wp4 = (const float4*)(white + (s0 + r0) * 49);
        const float4* bp4 = (const float4*)(black + (s0 + r0) * 49);

        // ---- pad zeros for own row (slots for cols 98..103) ---------------
        {
            int pb = (r0 + lane) * 104;
            shu[pb + 97] = 0; shu[pb + 99] = 0; shu[pb + 100] = 0;
            shu[pb + 101] = 0; shu[pb + 102] = 0; shu[pb + 103] = 0;
        }

        // ---- stage own 32 rows: 392 float4 per array, 2x6 batched + tail --
        {
            int s = s_init, k = k_init;
#pragma unroll 1
            for (int chunk = 0; chunk < 2; chunk++) {
                float4 wv[6], bv[6];
                int ss[6], kk[6];
#pragma unroll
                for (int u = 0; u < 6; u++) {
                    int idx4 = lane + 32 * (chunk * 6 + u);
                    wv[u] = wp4[idx4];
                    bv[u] = bp4[idx4];
                    ss[u] = s; kk[u] = k;
                    k += 30; s += 2; if (k >= 49) { k -= 49; s += 1; }
                }
#pragma unroll
                for (int u = 0; u < 6; u++)
                    scatter4(shu, r0, ss[u], kk[u], wv[u], bv[u]);
            }
            if (lane < 8) {   // j = 12: idx4 = lane + 384 < 392
                float4 w4 = wp4[lane + 384];
                float4 b4 = bp4[lane + 384];
                scatter4(shu, r0, s, k, w4, b4);
            }
        }
        __syncwarp();

        // ---- layer 1: D1[32x64] = X @ Wc^T, K=104, m=2 --------------------
        float acc1[2][8][4];
#pragma unroll
        for (int m = 0; m < 2; m++)
#pragma unroll
            for (int tn = 0; tn < 8; tn++)
#pragma unroll
                for (int r = 0; r < 4; r++) acc1[m][tn][r] = 0.0f;

#pragma unroll
        for (int s = 0; s < 13; s++) {
            uint2 aa[2][2];
#pragma unroll
            for (int m = 0; m < 2; m++)
#pragma unroll
                for (int h = 0; h < 2; h++)
                    aa[m][h] = *(const uint2*)&shu[(r0 + 16 * m + 8 * h + g) * 104
                                                   + (s * 4 + q) * 2];
#pragma unroll
            for (int tn = 0; tn < 8; tn++) {
                uint2 bv = *(const uint2*)&shu[U_BF1 + ((s * 8 + tn) * 32 + lane) * 2];
                mma8(acc1[0][tn], aa[0][0].x, aa[0][1].x, aa[0][0].y, aa[0][1].y, bv.x, bv.y);
                mma8(acc1[1][tn], aa[1][0].x, aa[1][1].x, aa[1][0].y, aa[1][1].y, bv.x, bv.y);
            }
        }
        __syncwarp();   // own-warp raw reads done before base overlay

        // ---- epilogue 1: bias + pov mix + relu -> base (in-place [0,64)) --
#pragma unroll
        for (int m = 0; m < 2; m++)
#pragma unroll
            for (int h = 0; h < 2; h++) {
                int row = r0 + 16 * m + 8 * h + g;
                float p  = pov[s0 + row];
                float q1 = 1.0f - p;
#pragma unroll
                for (int tn = 0; tn < 4; tn++)
#pragma unroll
                    for (int c = 0; c < 2; c++) {
                        int col = 8 * tn + 2 * q + c;
                        float lo = acc1[m][tn][2 * h + c]     + shf[U_BIAS1 + col];
                        float hi = acc1[m][tn + 4][2 * h + c] + shf[U_BIAS1 + 32 + col];
                        float v0 = fmaxf(p * lo + q1 * hi, 0.0f);
                        float v1 = fmaxf(p * hi + q1 * lo, 0.0f);
                        shu[row * 104 + coff(col)]      = f2tf32(v0);
                        shu[row * 104 + coff(col + 32)] = f2tf32(v1);
                    }
            }
        __syncwarp();

        // ---- layer 2: D2[32x32] = base @ W0^T, K=64 -----------------------
        float acc2[2][4][4];
#pragma unroll
        for (int m = 0; m < 2; m++)
#pragma unroll
            for (int tn = 0; tn < 4; tn++)
#pragma unroll
                for (int r = 0; r < 4; r++) acc2[m][tn][r] = 0.0f;

#pragma unroll
        for (int s = 0; s < 8; s++) {
            uint2 aa[2][2];
#pragma unroll
            for (int m = 0; m < 2; m++)
#pragma unroll
                for (int h = 0; h < 2; h++)
                    aa[m][h] = *(const uint2*)&shu[(r0 + 16 * m + 8 * h + g) * 104
                                                   + (s * 4 + q) * 2];
#pragma unroll
            for (int tn = 0; tn < 4; tn++) {
                uint2 bv = *(const uint2*)&shu[U_BF2 + ((s * 4 + tn) * 32 + lane) * 2];
                mma8(acc2[0][tn], aa[0][0].x, aa[0][1].x, aa[0][0].y, aa[0][1].y, bv.x, bv.y);
                mma8(acc2[1][tn], aa[1][0].x, aa[1][1].x, aa[1][0].y, aa[1][1].y, bv.x, bv.y);
            }
        }
        __syncwarp();

        // ---- epilogue 2: x0 = relu(D2+b0) -> [64,96); W2[0:32] partial dot
        float dot[2][2] = {{0.0f, 0.0f}, {0.0f, 0.0f}};
#pragma unroll
        for (int m = 0; m < 2; m++)
#pragma unroll
            for (int h = 0; h < 2; h++) {
                int row = r0 + 16 * m + 8 * h + g;
#pragma unroll
                for (int tn = 0; tn < 4; tn++)
#pragma unroll
                    for (int c = 0; c < 2; c++) {
                        int col = 8 * tn + 2 * q + c;
                        float v = fmaxf(acc2[m][tn][2 * h + c] + shf[U_B0 + col], 0.0f);
                        dot[m][h] += v * shf[U_W2 + col];
                        int r8 = col & 7;
                        shu[row * 104 + 64 + ((col & 24) | ((r8 & 3) << 1) | (r8 >> 2))]
                            = f2tf32(v);
                    }
            }
        __syncwarp();

        // ---- layer 3: D3[32x32] = x0 @ W1^T, K=32 -------------------------
        float acc3[2][4][4];
#pragma unroll
        for (int m = 0; m < 2; m++)
#pragma unroll
            for (int tn = 0; tn < 4; tn++)
#pragma unroll
                for (int r = 0; r < 4; r++) acc3[m][tn][r] = 0.0f;

#pragma unroll
        for (int s = 0; s < 4; s++) {
            uint2 aa[2][2];
#pragma unroll
            for (int m = 0; m < 2; m++)
#pragma unroll
                for (int h = 0; h < 2; h++)
                    aa[m][h] = *(const uint2*)&shu[(r0 + 16 * m + 8 * h + g) * 104
                                                   + 64 + (s * 4 + q) * 2];
#pragma unroll
            for (int tn = 0; tn < 4; tn++) {
                uint2 bv = *(const uint2*)&shu[U_BF3 + ((s * 4 + tn) * 32 + lane) * 2];
                mma8(acc3[0][tn], aa[0][0].x, aa[0][1].x, aa[0][0].y, aa[0][1].y, bv.x, bv.y);
                mma8(acc3[1][tn], aa[1][0].x, aa[1][1].x, aa[1][0].y, aa[1][1].y, bv.x, bv.y);
            }
        }

        // ---- epilogue 3: dot += relu(D3+b1).W2[32:]; reduce; store --------
#pragma unroll
        for (int m = 0; m < 2; m++)
#pragma unroll
            for (int h = 0; h < 2; h++) {
#pragma unroll
                for (int tn = 0; tn < 4; tn++)
#pragma unroll
                    for (int c = 0; c < 2; c++) {
                        int col = 8 * tn + 2 * q + c;
                        float v = fmaxf(acc3[m][tn][2 * h + c] + shf[U_B1 + col], 0.0f);
                        dot[m][h] += v * shf[U_W2 + 32 + col];
                    }
                float d = dot[m][h];
                d += __shfl_xor_sync(0xffffffffu, d, 1);
                d += __shfl_xor_sync(0xffffffffu, d, 2);
                if (q == 0)
                    out[s0 + r0 + 16 * m + 8 * h + g] = d + b2val;
            }
        __syncwarp();   // own rows free before next tile's staging
    }
}

// ---------------------------------------------------------------------------
extern "C" void kernel_launch(void* const* d_in, const int* in_sizes, int n_in,
                              void* d_out, int out_size) {
    const float* pov   = (const float*)d_in[0];
    const float* white = (const float*)d_in[1];
    const float* black = (const float*)d_in[2];
    const float* Ww    = (const float*)d_in[3];
    const float* bw    = (const float*)d_in[4];
    const float* Wb    = (const float*)d_in[5];
    const float* bb    = (const float*)d_in[6];
    const float* W0    = (const float*)d_in[7];
    const float* b0    = (const float*)d_in[8];
    const float* W1    = (const float*)d_in[9];
    const float* b1    = (const float*)d_in[10];
    const float* W2    = (const float*)d_in[11];
    const float* b2    = (const float*)d_in[12];

    const int B = in_sizes[0];
    const int ntiles = B / 256;

    cudaFuncSetAttribute(nnue_mma,
                         cudaFuncAttributeMaxDynamicSharedMemorySize, SMEM_BYTES);

    nnue_setup<<<26, 256>>>(Ww, Wb, W0, W1);
    nnue_mma<<<148, 256, SMEM_BYTES>>>(pov, white, black, bw, bb,
                                       b0, b1, W2, b2, (float*)d_out, ntiles);
}

// round 12
// speedup vs baseline: 5.4211x; 1.5544x over previous
#include <cuda_runtime.h>
#include <cstdint>

// ===========================================================================
// NNUE eval via tensor-core mma.sync (tf32, m16n8k8), compute_103-safe PTX.
// 148 persistent CTAs x 256 threads; warp owns 32 samples, fully private.
// X staged as a CONTIGUOUS cp.async copy (smem layout == global layout,
// raw fp32 bits fed to tf32 MMA = truncation).  Sample<->hw-row permutation
// sigma = 4g+2m+h makes all stride-49/66/34 LDS conflict-free.
// R11 fix: layer-1 s=6 straddle operand now includes +q (was reading
// garbage for lanes q>0 -> rel_err 0.11).
// ===========================================================================

__device__ __forceinline__ uint32_t f2tf32(float f) {
    uint32_t r; asm("cvt.rna.tf32.f32 %0, %1;" : "=r"(r) : "f"(f)); return r;
}

__device__ __forceinline__ void mma8(float* d,
                                     uint32_t a0, uint32_t a1, uint32_t a2, uint32_t a3,
                                     uint32_t b0, uint32_t b1) {
    asm volatile(
        "mma.sync.aligned.m16n8k8.row.col.f32.tf32.tf32.f32 "
        "{%0,%1,%2,%3}, {%4,%5,%6,%7}, {%8,%9}, {%0,%1,%2,%3};"
        : "+f"(d[0]), "+f"(d[1]), "+f"(d[2]), "+f"(d[3])
        : "r"(a0), "r"(a1), "r"(a2), "r"(a3), "r"(b0), "r"(b1));
}

#define CP16(dst, src) \
    asm volatile("cp.async.cg.shared.global [%0], [%1], 16;" :: "r"(dst), "l"(src))
#define CP_COMMIT() asm volatile("cp.async.commit_group;" ::: "memory")
#define CP_WAIT0()  asm volatile("cp.async.wait_group 0;" ::: "memory")

// ---- pre-packed per-lane B fragments (device globals) ---------------------
__device__ uint32_t g_Bf1[13 * 8 * 32 * 2];
__device__ uint32_t g_Bf2[8 * 4 * 32 * 2];
__device__ uint32_t g_Bf3[4 * 4 * 32 * 2];

__global__ void nnue_setup(const float* __restrict__ Ww,
                           const float* __restrict__ Wb,
                           const float* __restrict__ W0,
                           const float* __restrict__ W1) {
    int t = blockIdx.x * blockDim.x + threadIdx.x;
    if (t < 6656) {
        int e = t & 1, lane = (t >> 1) & 31, tn = (t >> 6) & 7, s = t >> 9;
        int n = 8 * tn + (lane >> 2);
        int k = 8 * s + (lane & 3) + 4 * e;
        float v = 0.0f;
        if (k < 98) {
            if (n < 32) v = Ww[n * 98 + k];
            else { int kk = k + 49; if (kk >= 98) kk -= 98; v = Wb[(n - 32) * 98 + kk]; }
        }
        g_Bf1[t] = f2tf32(v);
    }
    if (t < 2048) {
        int e = t & 1, lane = (t >> 1) & 31, tn = (t >> 6) & 3, s = t >> 8;
        int n = 8 * tn + (lane >> 2);
        int k = 8 * s + (lane & 3) + 4 * e;
        g_Bf2[t] = f2tf32(W0[n * 64 + k]);
    }
    if (t < 1024) {
        int e = t & 1, lane = (t >> 1) & 31, tn = (t >> 6) & 3, s = t >> 8;
        int n = 8 * tn + (lane >> 2);
        int k = 8 * s + (lane & 3) + 4 * e;
        g_Bf3[t] = f2tf32(W1[n * 32 + k]);
    }
}

// ---- smem u32 offsets -----------------------------------------------------
// Per-warp region 3136 u32: white[32*49] at +0, black[32*49] at +1568.
// After L1: base overlays at stride 66 (<=2109).  After L2: x0 overlays at
// stride 34 (<=1085).  All rewritten by next tile's cp.async copy.
#define U_WARPSZ 3136
#define U_BF1    25088
#define U_BF2    31744
#define U_BF3    33792
#define U_BIAS1  34816
#define U_B0     34880
#define U_B1     34912
#define U_W2     34944
#define U_B2     35008
#define SMEM_BYTES (35012 * 4)   // ~137 KB -> 1 CTA/SM

__global__ __launch_bounds__(256, 1)
void nnue_mma(const float* __restrict__ pov,
              const float* __restrict__ white,
              const float* __restrict__ black,
              const float* __restrict__ bw,
              const float* __restrict__ bb,
              const float* __restrict__ b0,
              const float* __restrict__ b1,
              const float* __restrict__ W2,
              const float* __restrict__ b2,
              float* __restrict__ out, int ntiles) {
    extern __shared__ __align__(16) uint32_t shu[];
    float* shf = (float*)shu;
    const int t = threadIdx.x;
    const int lane = t & 31, wid = t >> 5;
    const int g = lane >> 2, q = lane & 3;
    const int r0 = wid * 32;
    const int WR = wid * U_WARPSZ;

    // ---- one-time: fragments + vectors ------------------------------------
    {
        uint4* d = (uint4*)(shu + U_BF1); const uint4* s = (const uint4*)g_Bf1;
        for (int i = t; i < 1664; i += 256) d[i] = s[i];
        d = (uint4*)(shu + U_BF2); s = (const uint4*)g_Bf2;
        for (int i = t; i < 512; i += 256) d[i] = s[i];
        d = (uint4*)(shu + U_BF3); s = (const uint4*)g_Bf3;
        for (int i = t; i < 256; i += 256) d[i] = s[i];
    }
    if (t < 64) shf[U_BIAS1 + t] = (t < 32) ? bw[t] : bb[t - 32];
    if (t < 64) shf[U_W2 + t]    = W2[t];
    if (t < 32) shf[U_B0 + t]    = b0[t];
    if (t < 32) shf[U_B1 + t]    = b1[t];
    if (t == 0) shf[U_B2]        = b2[0];
    __syncthreads();

    // ---- preload all per-thread vectors into registers --------------------
    float blo[8], bhi[8], b0r[8], b1r[8], w2lo[8], w2hi[8];
#pragma unroll
    for (int i = 0; i < 8; i++) {
        int col = 8 * (i >> 1) + 2 * q + (i & 1);
        blo[i]  = shf[U_BIAS1 + col];
        bhi[i]  = shf[U_BIAS1 + 32 + col];
        b0r[i]  = shf[U_B0 + col];
        b1r[i]  = shf[U_B1 + col];
        w2lo[i] = shf[U_W2 + col];
        w2hi[i] = shf[U_W2 + 32 + col];
    }
    const float b2val = shf[U_B2];

    // ---- tile-invariant bases (sigma = 4g + 2m + h) -----------------------
    const int qadj = (q > 0) ? 1519 : 0;    // black-region jump for s=6 x1
    int sig[2][2];
    uint32_t rbq[2][2], rbB[2][2], rbB2[2][2], rbX[2][2], rbX2[2][2];
#pragma unroll
    for (int m = 0; m < 2; m++)
#pragma unroll
        for (int h = 0; h < 2; h++) {
            int s_ = 4 * g + 2 * m + h;
            sig[m][h]  = s_;
            rbq[m][h]  = WR + s_ * 49 + q;
            rbB[m][h]  = WR + s_ * 66;
            rbB2[m][h] = rbB[m][h] + 2 * q;
            rbX[m][h]  = WR + s_ * 34;
            rbX2[m][h] = rbX[m][h] + 2 * q;
        }
    const int ec0 = (((2 * q) & 3) << 1) | ((2 * q) >> 2);
    const int ec1 = (((2 * q + 1) & 3) << 1) | ((2 * q + 1) >> 2);
    const uint32_t bfb1 = U_BF1 + lane * 2;
    const uint32_t bfb2 = U_BF2 + lane * 2;
    const uint32_t bfb3 = U_BF3 + lane * 2;

    uint32_t sb;   // smem byte base
    asm("{ .reg .u64 t; cvta.to.shared.u64 t, %1; cvt.u32.u64 %0, t; }"
        : "=r"(sb) : "l"(shu));
    const uint32_t wdst = sb + WR * 4 + lane * 16;
    const uint32_t bdst = wdst + 1568 * 4;

    for (int tile = blockIdx.x; tile < ntiles; tile += gridDim.x) {
        const size_t s0 = (size_t)tile * 256;
        const char* wsrc = (const char*)(white + (s0 + r0) * 49) + lane * 16;
        const char* bsrc = (const char*)(black + (s0 + r0) * 49) + lane * 16;

        // ---- stage: contiguous cp.async copy (raw fp32 bits) --------------
#pragma unroll
        for (int j = 0; j < 12; j++) {
            CP16(wdst + j * 512, wsrc + j * 512);
            CP16(bdst + j * 512, bsrc + j * 512);
        }
        if (lane < 8) {
            CP16(wdst + 12 * 512, wsrc + 12 * 512);
            CP16(bdst + 12 * 512, bsrc + 12 * 512);
        }
        CP_COMMIT();
        CP_WAIT0();
        __syncwarp();

        // ---- layer 1: D1 = X @ Wc^T, K=104 (13 steps) ---------------------
        float acc1[2][8][4];
#pragma unroll
        for (int m = 0; m < 2; m++)
#pragma unroll
            for (int tn = 0; tn < 8; tn++)
#pragma unroll
                for (int r = 0; r < 4; r++) acc1[m][tn][r] = 0.0f;

#pragma unroll
        for (int s = 0; s < 13; s++) {
            uint32_t x1[2][2], x2[2][2];
#pragma unroll
            for (int m = 0; m < 2; m++)
#pragma unroll
                for (int h = 0; h < 2; h++) {
                    if (s < 6) {
                        x1[m][h] = shu[rbq[m][h] + 8 * s];
                        x2[m][h] = shu[rbq[m][h] + 8 * s + 4];
                    } else if (s == 6) {
                        // col 48+q: white elem 48 (q=0) / black elem q-1 (q>0)
                        x1[m][h] = shu[rbq[m][h] + 48 + qadj];
                        // col 52+q: black elem 3+q
                        x2[m][h] = shu[rbq[m][h] + 52 + 1519];
                    } else {
                        x1[m][h] = shu[rbq[m][h] + 8 * s + 1519];
                        x2[m][h] = shu[rbq[m][h] + 8 * s + 4 + 1519];
                    }
                }
#pragma unroll
            for (int tn = 0; tn < 8; tn++) {
                uint2 bv = *(const uint2*)&shu[bfb1 + (s * 8 + tn) * 64];
                mma8(acc1[0][tn], x1[0][0], x1[0][1], x2[0][0], x2[0][1], bv.x, bv.y);
                mma8(acc1[1][tn], x1[1][0], x1[1][1], x2[1][0], x2[1][1], bv.x, bv.y);
            }
        }
        __syncwarp();

        // ---- epilogue 1: bias + pov mix + relu -> base (stride 66) --------
#pragma unroll
        for (int m = 0; m < 2; m++)
#pragma unroll
            for (int h = 0; h < 2; h++) {
                float p  = pov[s0 + r0 + sig[m][h]];
                float q1 = 1.0f - p;
#pragma unroll
                for (int tn = 0; tn < 4; tn++)
#pragma unroll
                    for (int c = 0; c < 2; c++) {
                        int i = tn * 2 + c;
                        float lo = acc1[m][tn][2 * h + c]     + blo[i];
                        float hi = acc1[m][tn + 4][2 * h + c] + bhi[i];
                        float v0 = fmaxf(p * lo + q1 * hi, 0.0f);
                        float v1 = fmaxf(p * hi + q1 * lo, 0.0f);
                        int e = (c == 0) ? ec0 : ec1;
                        shu[rbB[m][h] + tn * 8 + e]      = f2tf32(v0);
                        shu[rbB[m][h] + tn * 8 + e + 32] = f2tf32(v1);
                    }
            }
        __syncwarp();

        // ---- layer 2: D2 = base @ W0^T, K=64 ------------------------------
        float acc2[2][4][4];
#pragma unroll
        for (int m = 0; m < 2; m++)
#pragma unroll
            for (int tn = 0; tn < 4; tn++)
#pragma unroll
                for (int r = 0; r < 4; r++) acc2[m][tn][r] = 0.0f;

#pragma unroll
        for (int s = 0; s < 8; s++) {
            uint2 av[2][2];
#pragma unroll
            for (int m = 0; m < 2; m++)
#pragma unroll
                for (int h = 0; h < 2; h++)
                    av[m][h] = *(const uint2*)&shu[rbB2[m][h] + s * 8];
#pragma unroll
            for (int tn = 0; tn < 4; tn++) {
                uint2 bv = *(const uint2*)&shu[bfb2 + (s * 4 + tn) * 64];
                mma8(acc2[0][tn], av[0][0].x, av[0][1].x, av[0][0].y, av[0][1].y, bv.x, bv.y);
                mma8(acc2[1][tn], av[1][0].x, av[1][1].x, av[1][0].y, av[1][1].y, bv.x, bv.y);
            }
        }
        __syncwarp();

        // ---- epilogue 2: x0 = relu(D2+b0) -> stride 34; W2[0:32] dot ------
        float dot[2][2] = {{0.0f, 0.0f}, {0.0f, 0.0f}};
#pragma unroll
        for (int m = 0; m < 2; m++)
#pragma unroll
            for (int h = 0; h < 2; h++)
#pragma unroll
                for (int tn = 0; tn < 4; tn++)
#pragma unroll
                    for (int c = 0; c < 2; c++) {
                        int i = tn * 2 + c;
                        float v = fmaxf(acc2[m][tn][2 * h + c] + b0r[i], 0.0f);
                        dot[m][h] += v * w2lo[i];
                        int e = (c == 0) ? ec0 : ec1;
                        shu[rbX[m][h] + tn * 8 + e] = f2tf32(v);
                    }
        __syncwarp();

        // ---- layer 3: D3 = x0 @ W1^T, K=32 --------------------------------
        float acc3[2][4][4];
#pragma unroll
        for (int m = 0; m < 2; m++)
#pragma unroll
            for (int tn = 0; tn < 4; tn++)
#pragma unroll
                for (int r = 0; r < 4; r++) acc3[m][tn][r] = 0.0f;

#pragma unroll
        for (int s = 0; s < 4; s++) {
            uint2 av[2][2];
#pragma unroll
            for (int m = 0; m < 2; m++)
#pragma unroll
                for (int h = 0; h < 2; h++)
                    av[m][h] = *(const uint2*)&shu[rbX2[m][h] + s * 8];
#pragma unroll
            for (int tn = 0; tn < 4; tn++) {
                uint2 bv = *(const uint2*)&shu[bfb3 + (s * 4 + tn) * 64];
                mma8(acc3[0][tn], av[0][0].x, av[0][1].x, av[0][0].y, av[0][1].y, bv.x, bv.y);
                mma8(acc3[1][tn], av[1][0].x, av[1][1].x, av[1][0].y, av[1][1].y, bv.x, bv.y);
            }
        }

        // ---- epilogue 3: dot += relu(D3+b1).W2[32:]; reduce; store --------
#pragma unroll
        for (int m = 0; m < 2; m++)
#pragma unroll
            for (int h = 0; h < 2; h++) {
#pragma unroll
                for (int tn = 0; tn < 4; tn++)
#pragma unroll
                    for (int c = 0; c < 2; c++) {
                        int i = tn * 2 + c;
                        float v = fmaxf(acc3[m][tn][2 * h + c] + b1r[i], 0.0f);
                        dot[m][h] += v * w2hi[i];
                    }
                float d = dot[m][h];
                d += __shfl_xor_sync(0xffffffffu, d, 1);
                d += __shfl_xor_sync(0xffffffffu, d, 2);
                if (q == 0)
                    out[s0 + r0 + sig[m][h]] = d + b2val;
            }
        __syncwarp();
    }
}

// ---------------------------------------------------------------------------
extern "C" void kernel_launch(void* const* d_in, const int* in_sizes, int n_in,
                              void* d_out, int out_size) {
    const float* pov   = (const float*)d_in[0];
    const float* white = (const float*)d_in[1];
    const float* black = (const float*)d_in[2];
    const float* Ww    = (const float*)d_in[3];
    const float* bw    = (const float*)d_in[4];
    const float* Wb    = (const float*)d_in[5];
    const float* bb    = (const float*)d_in[6];
    const float* W0    = (const float*)d_in[7];
    const float* b0    = (const float*)d_in[8];
    const float* W1    = (const float*)d_in[9];
    const float* b1    = (const float*)d_in[10];
    const float* W2    = (const float*)d_in[11];
    const float* b2    = (const float*)d_in[12];

    const int B = in_sizes[0];
    const int ntiles = B / 256;

    cudaFuncSetAttribute(nnue_mma,
                         cudaFuncAttributeMaxDynamicSharedMemorySize, SMEM_BYTES);

    nnue_setup<<<26, 256>>>(Ww, Wb, W0, W1);
    nnue_mma<<<148, 256, SMEM_BYTES>>>(pov, white, black, bw, bb,
                                       b0, b1, W2, b2, (float*)d_out, ntiles);
}

// round 13
// speedup vs baseline: 6.0459x; 1.1153x over previous
#include <cuda_runtime.h>
#include <cstdint>

// ===========================================================================
// NNUE eval via tensor-core mma.sync (tf32, m16n8k8), compute_103-safe PTX.
// 148 persistent CTAs x 256 threads; warp owns 32 samples, fully private.
// X staged as a CONTIGUOUS cp.async copy; R13: staging is PIPELINED —
// next tile's cp.async issues right after layer-1's last X read; base/x0
// overlays moved to a dedicated BX region so X stays prefetch-targetable.
// Sample<->hw-row permutation sigma = 4g+2m+h keeps stride-49/66/34 LDS
// conflict-free.  BX is zero-filled once (s=12 overflow reads land there:
// finite * 0-weight, never NaN).
// ===========================================================================

__device__ __forceinline__ uint32_t f2tf32(float f) {
    uint32_t r; asm("cvt.rna.tf32.f32 %0, %1;" : "=r"(r) : "f"(f)); return r;
}

__device__ __forceinline__ void mma8(float* d,
                                     uint32_t a0, uint32_t a1, uint32_t a2, uint32_t a3,
                                     uint32_t b0, uint32_t b1) {
    asm volatile(
        "mma.sync.aligned.m16n8k8.row.col.f32.tf32.tf32.f32 "
        "{%0,%1,%2,%3}, {%4,%5,%6,%7}, {%8,%9}, {%0,%1,%2,%3};"
        : "+f"(d[0]), "+f"(d[1]), "+f"(d[2]), "+f"(d[3])
        : "r"(a0), "r"(a1), "r"(a2), "r"(a3), "r"(b0), "r"(b1));
}

#define CP16(dst, src) \
    asm volatile("cp.async.cg.shared.global [%0], [%1], 16;" :: "r"(dst), "l"(src))
#define CP_COMMIT() asm volatile("cp.async.commit_group;" ::: "memory")
#define CP_WAIT0()  asm volatile("cp.async.wait_group 0;" ::: "memory")

// ---- pre-packed per-lane B fragments (device globals) ---------------------
__device__ uint32_t g_Bf1[13 * 8 * 32 * 2];
__device__ uint32_t g_Bf2[8 * 4 * 32 * 2];
__device__ uint32_t g_Bf3[4 * 4 * 32 * 2];

__global__ void nnue_setup(const float* __restrict__ Ww,
                           const float* __restrict__ Wb,
                           const float* __restrict__ W0,
                           const float* __restrict__ W1) {
    int t = blockIdx.x * blockDim.x + threadIdx.x;
    if (t < 6656) {
        int e = t & 1, lane = (t >> 1) & 31, tn = (t >> 6) & 7, s = t >> 9;
        int n = 8 * tn + (lane >> 2);
        int k = 8 * s + (lane & 3) + 4 * e;
        float v = 0.0f;
        if (k < 98) {
            if (n < 32) v = Ww[n * 98 + k];
            else { int kk = k + 49; if (kk >= 98) kk -= 98; v = Wb[(n - 32) * 98 + kk]; }
        }
        g_Bf1[t] = f2tf32(v);
    }
    if (t < 2048) {
        int e = t & 1, lane = (t >> 1) & 31, tn = (t >> 6) & 3, s = t >> 8;
        int n = 8 * tn + (lane >> 2);
        int k = 8 * s + (lane & 3) + 4 * e;
        g_Bf2[t] = f2tf32(W0[n * 64 + k]);
    }
    if (t < 1024) {
        int e = t & 1, lane = (t >> 1) & 31, tn = (t >> 6) & 3, s = t >> 8;
        int n = 8 * tn + (lane >> 2);
        int k = 8 * s + (lane & 3) + 4 * e;
        g_Bf3[t] = f2tf32(W1[n * 32 + k]);
    }
}

// ---- smem u32 offsets -----------------------------------------------------
// X: 8 warps x 3136 (white[1568] + black[1568], contiguous global layout).
// BX: 8 warps x 2112: base at stride 66 (written epi1, read L2); x0 at
// stride 34 overlays base's dead space (written epi2, read L3).
#define U_XSZ   3136
#define U_BXSZ  2112
#define U_BX    25088
#define U_BF1   41984
#define U_BF2   48640
#define U_BF3   50688
#define U_BIAS1 51712
#define U_B0    51776
#define U_B1    51808
#define U_W2    51840
#define U_B2    51904
#define SMEM_BYTES (51908 * 4)   // ~203 KB -> 1 CTA/SM

__global__ __launch_bounds__(256, 1)
void nnue_mma(const float* __restrict__ pov,
              const float* __restrict__ white,
              const float* __restrict__ black,
              const float* __restrict__ bw,
              const float* __restrict__ bb,
              const float* __restrict__ b0,
              const float* __restrict__ b1,
              const float* __restrict__ W2,
              const float* __restrict__ b2,
              float* __restrict__ out, int ntiles) {
    extern __shared__ __align__(16) uint32_t shu[];
    float* shf = (float*)shu;
    const int t = threadIdx.x;
    const int lane = t & 31, wid = t >> 5;
    const int g = lane >> 2, q = lane & 3;
    const int r0 = wid * 32;
    const int WR = wid * U_XSZ;
    const int BXR = U_BX + wid * U_BXSZ;

    // ---- one-time: fragments + vectors + BX zero-fill ---------------------
    {
        uint4* d = (uint4*)(shu + U_BF1); const uint4* s = (const uint4*)g_Bf1;
        for (int i = t; i < 1664; i += 256) d[i] = s[i];
        d = (uint4*)(shu + U_BF2); s = (const uint4*)g_Bf2;
        for (int i = t; i < 512; i += 256) d[i] = s[i];
        d = (uint4*)(shu + U_BF3); s = (const uint4*)g_Bf3;
        for (int i = t; i < 256; i += 256) d[i] = s[i];
    }
    for (int i = t; i < 8 * U_BXSZ; i += 256) shu[U_BX + i] = 0;
    if (t < 64) shf[U_BIAS1 + t] = (t < 32) ? bw[t] : bb[t - 32];
    if (t < 64) shf[U_W2 + t]    = W2[t];
    if (t < 32) shf[U_B0 + t]    = b0[t];
    if (t < 32) shf[U_B1 + t]    = b1[t];
    if (t == 0) shf[U_B2]        = b2[0];
    __syncthreads();

    // ---- preload all per-thread vectors into registers --------------------
    float blo[8], bhi[8], b0r[8], b1r[8], w2lo[8], w2hi[8];
#pragma unroll
    for (int i = 0; i < 8; i++) {
        int col = 8 * (i >> 1) + 2 * q + (i & 1);
        blo[i]  = shf[U_BIAS1 + col];
        bhi[i]  = shf[U_BIAS1 + 32 + col];
        b0r[i]  = shf[U_B0 + col];
        b1r[i]  = shf[U_B1 + col];
        w2lo[i] = shf[U_W2 + col];
        w2hi[i] = shf[U_W2 + 32 + col];
    }
    const float b2val = shf[U_B2];

    // ---- tile-invariant bases (sigma = 4g + 2m + h) -----------------------
    const int qadj = (q > 0) ? 1519 : 0;    // black-region jump for s=6 x1
    int sig[2][2];
    uint32_t rbq[2][2], rbB[2][2], rbB2[2][2], rbX[2][2], rbX2[2][2];
#pragma unroll
    for (int m = 0; m < 2; m++)
#pragma unroll
        for (int h = 0; h < 2; h++) {
            int s_ = 4 * g + 2 * m + h;
            sig[m][h]  = s_;
            rbq[m][h]  = WR + s_ * 49 + q;
            rbB[m][h]  = BXR + s_ * 66;
            rbB2[m][h] = rbB[m][h] + 2 * q;
            rbX[m][h]  = BXR + s_ * 34;
            rbX2[m][h] = rbX[m][h] + 2 * q;
        }
    const int ec0 = (((2 * q) & 3) << 1) | ((2 * q) >> 2);
    const int ec1 = (((2 * q + 1) & 3) << 1) | ((2 * q + 1) >> 2);
    const uint32_t bfb1 = U_BF1 + lane * 2;
    const uint32_t bfb2 = U_BF2 + lane * 2;
    const uint32_t bfb3 = U_BF3 + lane * 2;

    uint32_t sb;   // smem byte base
    asm("{ .reg .u64 t; cvta.to.shared.u64 t, %1; cvt.u32.u64 %0, t; }"
        : "=r"(sb) : "l"(shu));
    const uint32_t wdst = sb + WR * 4 + lane * 16;
    const uint32_t bdst = wdst + 1568 * 4;

    // ---- staging issuer (one cp.async group per call) ---------------------
    auto stage = [&](int tile_) {
        const size_t sbase = ((size_t)tile_ * 256 + r0) * 49;
        const char* ws = (const char*)(white + sbase) + lane * 16;
        const char* bs = (const char*)(black + sbase) + lane * 16;
#pragma unroll
        for (int j = 0; j < 12; j++) {
            CP16(wdst + j * 512, ws + j * 512);
            CP16(bdst + j * 512, bs + j * 512);
        }
        if (lane < 8) {
            CP16(wdst + 12 * 512, ws + 12 * 512);
            CP16(bdst + 12 * 512, bs + 12 * 512);
        }
        CP_COMMIT();
    };

    int tile = blockIdx.x;
    if (tile < ntiles) stage(tile);

    for (; tile < ntiles; tile += gridDim.x) {
        const size_t s0 = (size_t)tile * 256;

        CP_WAIT0();
        __syncwarp();

        // ---- layer 1: D1 = X @ Wc^T, K=104 (13 steps) ---------------------
        float acc1[2][8][4];
#pragma unroll
        for (int m = 0; m < 2; m++)
#pragma unroll
            for (int tn = 0; tn < 8; tn++)
#pragma unroll
                for (int r = 0; r < 4; r++) acc1[m][tn][r] = 0.0f;

#pragma unroll
        for (int s = 0; s < 13; s++) {
            uint32_t x1[2][2], x2[2][2];
#pragma unroll
            for (int m = 0; m < 2; m++)
#pragma unroll
                for (int h = 0; h < 2; h++) {
                    if (s < 6) {
                        x1[m][h] = shu[rbq[m][h] + 8 * s];
                        x2[m][h] = shu[rbq[m][h] + 8 * s + 4];
                    } else if (s == 6) {
                        x1[m][h] = shu[rbq[m][h] + 48 + qadj];
                        x2[m][h] = shu[rbq[m][h] + 52 + 1519];
                    } else {
                        x1[m][h] = shu[rbq[m][h] + 8 * s + 1519];
                        x2[m][h] = shu[rbq[m][h] + 8 * s + 4 + 1519];
                    }
                }
#pragma unroll
            for (int tn = 0; tn < 8; tn++) {
                uint2 bv = *(const uint2*)&shu[bfb1 + (s * 8 + tn) * 64];
                mma8(acc1[0][tn], x1[0][0], x1[0][1], x2[0][0], x2[0][1], bv.x, bv.y);
                mma8(acc1[1][tn], x1[1][0], x1[1][1], x2[1][0], x2[1][1], bv.x, bv.y);
            }
        }

        // ---- prefetch next tile's X (X has no readers past this point) ----
        {
            int nxt = tile + gridDim.x;
            if (nxt < ntiles) stage(nxt);
        }

        // ---- epilogue 1: bias + pov mix + relu -> base (stride 66) --------
#pragma unroll
        for (int m = 0; m < 2; m++)
#pragma unroll
            for (int h = 0; h < 2; h++) {
                float p  = pov[s0 + r0 + sig[m][h]];
                float q1 = 1.0f - p;
#pragma unroll
                for (int tn = 0; tn < 4; tn++)
#pragma unroll
                    for (int c = 0; c < 2; c++) {
                        int i = tn * 2 + c;
                        float lo = acc1[m][tn][2 * h + c]     + blo[i];
                        float hi = acc1[m][tn + 4][2 * h + c] + bhi[i];
                        float v0 = fmaxf(p * lo + q1 * hi, 0.0f);
                        float v1 = fmaxf(p * hi + q1 * lo, 0.0f);
                        int e = (c == 0) ? ec0 : ec1;
                        shu[rbB[m][h] + tn * 8 + e]      = f2tf32(v0);
                        shu[rbB[m][h] + tn * 8 + e + 32] = f2tf32(v1);
                    }
            }
        __syncwarp();

        // ---- layer 2: D2 = base @ W0^T, K=64 ------------------------------
        float acc2[2][4][4];
#pragma unroll
        for (int m = 0; m < 2; m++)
#pragma unroll
            for (int tn = 0; tn < 4; tn++)
#pragma unroll
                for (int r = 0; r < 4; r++) acc2[m][tn][r] = 0.0f;

#pragma unroll
        for (int s = 0; s < 8; s++) {
            uint2 av[2][2];
#pragma unroll
            for (int m = 0; m < 2; m++)
#pragma unroll
                for (int h = 0; h < 2; h++)
                    av[m][h] = *(const uint2*)&shu[rbB2[m][h] + s * 8];
#pragma unroll
            for (int tn = 0; tn < 4; tn++) {
                uint2 bv = *(const uint2*)&shu[bfb2 + (s * 4 + tn) * 64];
                mma8(acc2[0][tn], av[0][0].x, av[0][1].x, av[0][0].y, av[0][1].y, bv.x, bv.y);
                mma8(acc2[1][tn], av[1][0].x, av[1][1].x, av[1][0].y, av[1][1].y, bv.x, bv.y);
            }
        }
        __syncwarp();

        // ---- epilogue 2: x0 = relu(D2+b0) -> stride 34; W2[0:32] dot ------
        float dot[2][2] = {{0.0f, 0.0f}, {0.0f, 0.0f}};
#pragma unroll
        for (int m = 0; m < 2; m++)
#pragma unroll
            for (int h = 0; h < 2; h++)
#pragma unroll
                for (int tn = 0; tn < 4; tn++)
#pragma unroll
                    for (int c = 0; c < 2; c++) {
                        int i = tn * 2 + c;
                        float v = fmaxf(acc2[m][tn][2 * h + c] + b0r[i], 0.0f);
                        dot[m][h] += v * w2lo[i];
                        int e = (c == 0) ? ec0 : ec1;
                        shu[rbX[m][h] + tn * 8 + e] = f2tf32(v);
                    }
        __syncwarp();

        // ---- layer 3: D3 = x0 @ W1^T, K=32 --------------------------------
        float acc3[2][4][4];
#pragma unroll
        for (int m = 0; m < 2; m++)
#pragma unroll
            for (int tn = 0; tn < 4; tn++)
#pragma unroll
                for (int r = 0; r < 4; r++) acc3[m][tn][r] = 0.0f;

#pragma unroll
        for (int s = 0; s < 4; s++) {
            uint2 av[2][2];
#pragma unroll
            for (int m = 0; m < 2; m++)
#pragma unroll
                for (int h = 0; h < 2; h++)
                    av[m][h] = *(const uint2*)&shu[rbX2[m][h] + s * 8];
#pragma unroll
            for (int tn = 0; tn < 4; tn++) {
                uint2 bv = *(const uint2*)&shu[bfb3 + (s * 4 + tn) * 64];
                mma8(acc3[0][tn], av[0][0].x, av[0][1].x, av[0][0].y, av[0][1].y, bv.x, bv.y);
                mma8(acc3[1][tn], av[1][0].x, av[1][1].x, av[1][0].y, av[1][1].y, bv.x, bv.y);
            }
        }

        // ---- epilogue 3: dot += relu(D3+b1).W2[32:]; reduce; store --------
#pragma unroll
        for (int m = 0; m < 2; m++)
#pragma unroll
            for (int h = 0; h < 2; h++) {
#pragma unroll
                for (int tn = 0; tn < 4; tn++)
#pragma unroll
                    for (int c = 0; c < 2; c++) {
                        int i = tn * 2 + c;
                        float v = fmaxf(acc3[m][tn][2 * h + c] + b1r[i], 0.0f);
                        dot[m][h] += v * w2hi[i];
                    }
                float d = dot[m][h];
                d += __shfl_xor_sync(0xffffffffu, d, 1);
                d += __shfl_xor_sync(0xffffffffu, d, 2);
                if (q == 0)
                    out[s0 + r0 + sig[m][h]] = d + b2val;
            }
        __syncwarp();
    }
}

// ---------------------------------------------------------------------------
extern "C" void kernel_launch(void* const* d_in, const int* in_sizes, int n_in,
                              void* d_out, int out_size) {
    const float* pov   = (const float*)d_in[0];
    const float* white = (const float*)d_in[1];
    const float* black = (const float*)d_in[2];
    const float* Ww    = (const float*)d_in[3];
    const float* bw    = (const float*)d_in[4];
    const float* Wb    = (const float*)d_in[5];
    const float* bb    = (const float*)d_in[6];
    const float* W0    = (const float*)d_in[7];
    const float* b0    = (const float*)d_in[8];
    const float* W1    = (const float*)d_in[9];
    const float* b1    = (const float*)d_in[10];
    const float* W2    = (const float*)d_in[11];
    const float* b2    = (const float*)d_in[12];

    const int B = in_sizes[0];
    const int ntiles = B / 256;

    cudaFuncSetAttribute(nnue_mma,
                         cudaFuncAttributeMaxDynamicSharedMemorySize, SMEM_BYTES);

    nnue_setup<<<26, 256>>>(Ww, Wb, W0, W1);
    nnue_mma<<<148, 256, SMEM_BYTES>>>(pov, white, black, bw, bb,
                                       b0, b1, W2, b2, (float*)d_out, ntiles);
}

// round 14
// speedup vs baseline: 6.4275x; 1.0631x over previous
#include <cuda_runtime.h>
#include <cstdint>

// ===========================================================================
// NNUE eval via tensor-core mma.sync (tf32, m16n8k8), compute_103-safe PTX.
// 148 persistent CTAs x 256 threads; warp owns 32 samples, fully private.
// R14: (1) split prefetch — white half of next tile issues mid-L1 (after
// K-step 6, when white cols are dead), black after L1; (2) pov prefetched
// into regs before L1; (3) L1/L2 B-fragments repacked for LDS.128 tn-pair
// loads; (4) L3 B-fragments held permanently in registers.
// ===========================================================================

__device__ __forceinline__ uint32_t f2tf32(float f) {
    uint32_t r; asm("cvt.rna.tf32.f32 %0, %1;" : "=r"(r) : "f"(f)); return r;
}

__device__ __forceinline__ void mma8(float* d,
                                     uint32_t a0, uint32_t a1, uint32_t a2, uint32_t a3,
                                     uint32_t b0, uint32_t b1) {
    asm volatile(
        "mma.sync.aligned.m16n8k8.row.col.f32.tf32.tf32.f32 "
        "{%0,%1,%2,%3}, {%4,%5,%6,%7}, {%8,%9}, {%0,%1,%2,%3};"
        : "+f"(d[0]), "+f"(d[1]), "+f"(d[2]), "+f"(d[3])
        : "r"(a0), "r"(a1), "r"(a2), "r"(a3), "r"(b0), "r"(b1));
}

#define CP16(dst, src) \
    asm volatile("cp.async.cg.shared.global [%0], [%1], 16;" :: "r"(dst), "l"(src))
#define CP_COMMIT() asm volatile("cp.async.commit_group;" ::: "memory")
#define CP_WAIT0()  asm volatile("cp.async.wait_group 0;" ::: "memory")

// ---- pre-packed per-lane B fragments (device globals) ---------------------
// Bf1/Bf2: tn-PAIR layout for LDS.128: idx = (s*NTP + tp)*128 + lane*4 + j,
//   j = (tn&1? 2:0) + e  -> uint4 = {tn0.e0, tn0.e1, tn1.e0, tn1.e1}.
// Bf3: old (s*4+tn)*64 + lane*2 layout (preloaded to regs once).
__device__ uint32_t g_Bf1[13 * 8 * 32 * 2];
__device__ uint32_t g_Bf2[8 * 4 * 32 * 2];
__device__ uint32_t g_Bf3[4 * 4 * 32 * 2];

__global__ void nnue_setup(const float* __restrict__ Ww,
                           const float* __restrict__ Wb,
                           const float* __restrict__ W0,
                           const float* __restrict__ W1) {
    int t = blockIdx.x * blockDim.x + threadIdx.x;
    if (t < 6656) {   // L1: 13 steps x 4 tn-pairs x 32 lanes x 4
        int j = t & 3, lane = (t >> 2) & 31, tp = (t >> 7) & 3, s = t >> 9;
        int tn = 2 * tp + (j >> 1), e = j & 1;
        int n = 8 * tn + (lane >> 2);
        int k = 8 * s + (lane & 3) + 4 * e;
        float v = 0.0f;
        if (k < 98) {
            if (n < 32) v = Ww[n * 98 + k];
            else { int kk = k + 49; if (kk >= 98) kk -= 98; v = Wb[(n - 32) * 98 + kk]; }
        }
        g_Bf1[t] = f2tf32(v);
    }
    if (t < 2048) {   // L2: 8 steps x 2 tn-pairs x 32 lanes x 4
        int j = t & 3, lane = (t >> 2) & 31, tp = (t >> 7) & 1, s = t >> 8;
        int tn = 2 * tp + (j >> 1), e = j & 1;
        int n = 8 * tn + (lane >> 2);
        int k = 8 * s + (lane & 3) + 4 * e;
        g_Bf2[t] = f2tf32(W0[n * 64 + k]);
    }
    if (t < 1024) {   // L3: old layout
        int e = t & 1, lane = (t >> 1) & 31, tn = (t >> 6) & 3, s = t >> 8;
        int n = 8 * tn + (lane >> 2);
        int k = 8 * s + (lane & 3) + 4 * e;
        g_Bf3[t] = f2tf32(W1[n * 32 + k]);
    }
}

// ---- smem u32 offsets -----------------------------------------------------
#define U_XSZ   3136
#define U_BXSZ  2112
#define U_BX    25088
#define U_BF1   41984
#define U_BF2   48640
#define U_BF3   50688
#define U_BIAS1 51712
#define U_B0    51776
#define U_B1    51808
#define U_W2    51840
#define U_B2    51904
#define SMEM_BYTES (51908 * 4)   // ~203 KB -> 1 CTA/SM

__global__ __launch_bounds__(256, 1)
void nnue_mma(const float* __restrict__ pov,
              const float* __restrict__ white,
              const float* __restrict__ black,
              const float* __restrict__ bw,
              const float* __restrict__ bb,
              const float* __restrict__ b0,
              const float* __restrict__ b1,
              const float* __restrict__ W2,
              const float* __restrict__ b2,
              float* __restrict__ out, int ntiles) {
    extern __shared__ __align__(16) uint32_t shu[];
    float* shf = (float*)shu;
    const int t = threadIdx.x;
    const int lane = t & 31, wid = t >> 5;
    const int g = lane >> 2, q = lane & 3;
    const int r0 = wid * 32;
    const int WR = wid * U_XSZ;
    const int BXR = U_BX + wid * U_BXSZ;

    // ---- one-time: fragments + vectors + BX zero-fill ---------------------
    {
        uint4* d = (uint4*)(shu + U_BF1); const uint4* s = (const uint4*)g_Bf1;
        for (int i = t; i < 1664; i += 256) d[i] = s[i];
        d = (uint4*)(shu + U_BF2); s = (const uint4*)g_Bf2;
        for (int i = t; i < 512; i += 256) d[i] = s[i];
        d = (uint4*)(shu + U_BF3); s = (const uint4*)g_Bf3;
        for (int i = t; i < 256; i += 256) d[i] = s[i];
    }
    for (int i = t; i < 8 * U_BXSZ; i += 256) shu[U_BX + i] = 0;
    if (t < 64) shf[U_BIAS1 + t] = (t < 32) ? bw[t] : bb[t - 32];
    if (t < 64) shf[U_W2 + t]    = W2[t];
    if (t < 32) shf[U_B0 + t]    = b0[t];
    if (t < 32) shf[U_B1 + t]    = b1[t];
    if (t == 0) shf[U_B2]        = b2[0];
    __syncthreads();

    // ---- preload per-thread vectors + L3 B-fragments into registers -------
    float blo[8], bhi[8], b0r[8], b1r[8], w2lo[8], w2hi[8];
#pragma unroll
    for (int i = 0; i < 8; i++) {
        int col = 8 * (i >> 1) + 2 * q + (i & 1);
        blo[i]  = shf[U_BIAS1 + col];
        bhi[i]  = shf[U_BIAS1 + 32 + col];
        b0r[i]  = shf[U_B0 + col];
        b1r[i]  = shf[U_B1 + col];
        w2lo[i] = shf[U_W2 + col];
        w2hi[i] = shf[U_W2 + 32 + col];
    }
    const float b2val = shf[U_B2];
    uint2 b3r[4][4];
#pragma unroll
    for (int s = 0; s < 4; s++)
#pragma unroll
        for (int tn = 0; tn < 4; tn++)
            b3r[s][tn] = *(const uint2*)&shu[U_BF3 + (s * 4 + tn) * 64 + lane * 2];

    // ---- tile-invariant bases (sigma = 4g + 2m + h) -----------------------
    const int qadj = (q > 0) ? 1519 : 0;
    int sig[2][2];
    uint32_t rbq[2][2], rbB[2][2], rbB2[2][2], rbX[2][2], rbX2[2][2];
#pragma unroll
    for (int m = 0; m < 2; m++)
#pragma unroll
        for (int h = 0; h < 2; h++) {
            int s_ = 4 * g + 2 * m + h;
            sig[m][h]  = s_;
            rbq[m][h]  = WR + s_ * 49 + q;
            rbB[m][h]  = BXR + s_ * 66;
            rbB2[m][h] = rbB[m][h] + 2 * q;
            rbX[m][h]  = BXR + s_ * 34;
            rbX2[m][h] = rbX[m][h] + 2 * q;
        }
    const int ec0 = (((2 * q) & 3) << 1) | ((2 * q) >> 2);
    const int ec1 = (((2 * q + 1) & 3) << 1) | ((2 * q + 1) >> 2);
    const uint32_t bfb1 = U_BF1 + lane * 4;
    const uint32_t bfb2 = U_BF2 + lane * 4;

    uint32_t sb;
    asm("{ .reg .u64 t; cvta.to.shared.u64 t, %1; cvt.u32.u64 %0, t; }"
        : "=r"(sb) : "l"(shu));
    const uint32_t wdst = sb + WR * 4 + lane * 16;
    const uint32_t bdst = wdst + 1568 * 4;

    // ---- staging issuers (one cp.async group per call) --------------------
    auto stage_w = [&](int tile_) {
        const char* ws = (const char*)(white + ((size_t)tile_ * 256 + r0) * 49)
                         + lane * 16;
#pragma unroll
        for (int j = 0; j < 12; j++) CP16(wdst + j * 512, ws + j * 512);
        if (lane < 8) CP16(wdst + 12 * 512, ws + 12 * 512);
        CP_COMMIT();
    };
    auto stage_b = [&](int tile_) {
        const char* bs = (const char*)(black + ((size_t)tile_ * 256 + r0) * 49)
                         + lane * 16;
#pragma unroll
        for (int j = 0; j < 12; j++) CP16(bdst + j * 512, bs + j * 512);
        if (lane < 8) CP16(bdst + 12 * 512, bs + 12 * 512);
        CP_COMMIT();
    };

    int tile = blockIdx.x;
    if (tile < ntiles) { stage_w(tile); stage_b(tile); }

    for (; tile < ntiles; tile += gridDim.x) {
        const size_t s0 = (size_t)tile * 256;
        const int nxt = tile + gridDim.x;
        const bool hasnxt = nxt < ntiles;

        CP_WAIT0();
        __syncwarp();

        // ---- prefetch pov into regs (consumed in epi1) --------------------
        float pv[2][2];
#pragma unroll
        for (int m = 0; m < 2; m++)
#pragma unroll
            for (int h = 0; h < 2; h++)
                pv[m][h] = pov[s0 + r0 + sig[m][h]];

        // ---- layer 1: D1 = X @ Wc^T, K=104 (13 steps) ---------------------
        float acc1[2][8][4];
#pragma unroll
        for (int m = 0; m < 2; m++)
#pragma unroll
            for (int tn = 0; tn < 8; tn++)
#pragma unroll
                for (int r = 0; r < 4; r++) acc1[m][tn][r] = 0.0f;

        // steps 0..6 (white reads finish at s=6)
#pragma unroll
        for (int s = 0; s < 7; s++) {
            uint32_t x1[2][2], x2[2][2];
#pragma unroll
            for (int m = 0; m < 2; m++)
#pragma unroll
                for (int h = 0; h < 2; h++) {
                    if (s < 6) {
                        x1[m][h] = shu[rbq[m][h] + 8 * s];
                        x2[m][h] = shu[rbq[m][h] + 8 * s + 4];
                    } else {
                        x1[m][h] = shu[rbq[m][h] + 48 + qadj];
                        x2[m][h] = shu[rbq[m][h] + 52 + 1519];
                    }
                }
#pragma unroll
            for (int tp = 0; tp < 4; tp++) {
                uint4 bq = *(const uint4*)&shu[bfb1 + (s * 4 + tp) * 128];
                mma8(acc1[0][2*tp],   x1[0][0], x1[0][1], x2[0][0], x2[0][1], bq.x, bq.y);
                mma8(acc1[1][2*tp],   x1[1][0], x1[1][1], x2[1][0], x2[1][1], bq.x, bq.y);
                mma8(acc1[0][2*tp+1], x1[0][0], x1[0][1], x2[0][0], x2[0][1], bq.z, bq.w);
                mma8(acc1[1][2*tp+1], x1[1][0], x1[1][1], x2[1][0], x2[1][1], bq.z, bq.w);
            }
        }

        // white half of X is dead -> prefetch next tile's white NOW
        if (hasnxt) stage_w(nxt);

        // steps 7..12 (black region only)
#pragma unroll
        for (int s = 7; s < 13; s++) {
            uint32_t x1[2][2], x2[2][2];
#pragma unroll
            for (int m = 0; m < 2; m++)
#pragma unroll
                for (int h = 0; h < 2; h++) {
                    x1[m][h] = shu[rbq[m][h] + 8 * s + 1519];
                    x2[m][h] = shu[rbq[m][h] + 8 * s + 4 + 1519];
                }
#pragma unroll
            for (int tp = 0; tp < 4; tp++) {
                uint4 bq = *(const uint4*)&shu[bfb1 + (s * 4 + tp) * 128];
                mma8(acc1[0][2*tp],   x1[0][0], x1[0][1], x2[0][0], x2[0][1], bq.x, bq.y);
                mma8(acc1[1][2*tp],   x1[1][0], x1[1][1], x2[1][0], x2[1][1], bq.x, bq.y);
                mma8(acc1[0][2*tp+1], x1[0][0], x1[0][1], x2[0][0], x2[0][1], bq.z, bq.w);
                mma8(acc1[1][2*tp+1], x1[1][0], x1[1][1], x2[1][0], x2[1][1], bq.z, bq.w);
            }
        }

        // black half of X is dead -> prefetch next tile's black
        if (hasnxt) stage_b(nxt);

        // ---- epilogue 1: bias + pov mix + relu -> base (stride 66) --------
#pragma unroll
        for (int m = 0; m < 2; m++)
#pragma unroll
            for (int h = 0; h < 2; h++) {
                float p  = pv[m][h];
                float q1 = 1.0f - p;
#pragma unroll
                for (int tn = 0; tn < 4; tn++)
#pragma unroll
                    for (int c = 0; c < 2; c++) {
                        int i = tn * 2 + c;
                        float lo = acc1[m][tn][2 * h + c]     + blo[i];
                        float hi = acc1[m][tn + 4][2 * h + c] + bhi[i];
                        float v0 = fmaxf(p * lo + q1 * hi, 0.0f);
                        float v1 = fmaxf(p * hi + q1 * lo, 0.0f);
                        int e = (c == 0) ? ec0 : ec1;
                        shu[rbB[m][h] + tn * 8 + e]      = f2tf32(v0);
                        shu[rbB[m][h] + tn * 8 + e + 32] = f2tf32(v1);
                    }
            }
        __syncwarp();

        // ---- layer 2: D2 = base @ W0^T, K=64 ------------------------------
        float acc2[2][4][4];
#pragma unroll
        for (int m = 0; m < 2; m++)
#pragma unroll
            for (int tn = 0; tn < 4; tn++)
#pragma unroll
                for (int r = 0; r < 4; r++) acc2[m][tn][r] = 0.0f;

#pragma unroll
        for (int s = 0; s < 8; s++) {
            uint2 av[2][2];
#pragma unroll
            for (int m = 0; m < 2; m++)
#pragma unroll
                for (int h = 0; h < 2; h++)
                    av[m][h] = *(const uint2*)&shu[rbB2[m][h] + s * 8];
#pragma unroll
            for (int tp = 0; tp < 2; tp++) {
                uint4 bq = *(const uint4*)&shu[bfb2 + (s * 2 + tp) * 128];
                mma8(acc2[0][2*tp],   av[0][0].x, av[0][1].x, av[0][0].y, av[0][1].y, bq.x, bq.y);
                mma8(acc2[1][2*tp],   av[1][0].x, av[1][1].x, av[1][0].y, av[1][1].y, bq.x, bq.y);
                mma8(acc2[0][2*tp+1], av[0][0].x, av[0][1].x, av[0][0].y, av[0][1].y, bq.z, bq.w);
                mma8(acc2[1][2*tp+1], av[1][0].x, av[1][1].x, av[1][0].y, av[1][1].y, bq.z, bq.w);
            }
        }
        __syncwarp();

        // ---- epilogue 2: x0 = relu(D2+b0) -> stride 34; W2[0:32] dot ------
        float dot[2][2] = {{0.0f, 0.0f}, {0.0f, 0.0f}};
#pragma unroll
        for (int m = 0; m < 2; m++)
#pragma unroll
            for (int h = 0; h < 2; h++)
#pragma unroll
                for (int tn = 0; tn < 4; tn++)
#pragma unroll
                    for (int c = 0; c < 2; c++) {
                        int i = tn * 2 + c;
                        float v = fmaxf(acc2[m][tn][2 * h + c] + b0r[i], 0.0f);
                        dot[m][h] += v * w2lo[i];
                        int e = (c == 0) ? ec0 : ec1;
                        shu[rbX[m][h] + tn * 8 + e] = f2tf32(v);
                    }
        __syncwarp();

        // ---- layer 3: D3 = x0 @ W1^T, K=32 (B-frags in regs) --------------
        float acc3[2][4][4];
#pragma unroll
        for (int m = 0; m < 2; m++)
#pragma unroll
            for (int tn = 0; tn < 4; tn++)
#pragma unroll
                for (int r = 0; r < 4; r++) acc3[m][tn][r] = 0.0f;

#pragma unroll
        for (int s = 0; s < 4; s++) {
            uint2 av[2][2];
#pragma unroll
            for (int m = 0; m < 2; m++)
#pragma unroll
                for (int h = 0; h < 2; h++)
                    av[m][h] = *(const uint2*)&shu[rbX2[m][h] + s * 8];
#pragma unroll
            for (int tn = 0; tn < 4; tn++) {
                mma8(acc3[0][tn], av[0][0].x, av[0][1].x, av[0][0].y, av[0][1].y,
                     b3r[s][tn].x, b3r[s][tn].y);
                mma8(acc3[1][tn], av[1][0].x, av[1][1].x, av[1][0].y, av[1][1].y,
                     b3r[s][tn].x, b3r[s][tn].y);
            }
        }

        // ---- epilogue 3: dot += relu(D3+b1).W2[32:]; reduce; store --------
#pragma unroll
        for (int m = 0; m < 2; m++)
#pragma unroll
            for (int h = 0; h < 2; h++) {
#pragma unroll
                for (int tn = 0; tn < 4; tn++)
#pragma unroll
                    for (int c = 0; c < 2; c++) {
                        int i = tn * 2 + c;
                        float v = fmaxf(acc3[m][tn][2 * h + c] + b1r[i], 0.0f);
                        dot[m][h] += v * w2hi[i];
                    }
                float d = dot[m][h];
                d += __shfl_xor_sync(0xffffffffu, d, 1);
                d += __shfl_xor_sync(0xffffffffu, d, 2);
                if (q == 0)
                    out[s0 + r0 + sig[m][h]] = d + b2val;
            }
        __syncwarp();
    }
}

// ---------------------------------------------------------------------------
extern "C" void kernel_launch(void* const* d_in, const int* in_sizes, int n_in,
                              void* d_out, int out_size) {
    const float* pov   = (const float*)d_in[0];
    const float* white = (const float*)d_in[1];
    const float* black = (const float*)d_in[2];
    const float* Ww    = (const float*)d_in[3];
    const float* bw    = (const float*)d_in[4];
    const float* Wb    = (const float*)d_in[5];
    const float* bb    = (const float*)d_in[6];
    const float* W0    = (const float*)d_in[7];
    const float* b0    = (const float*)d_in[8];
    const float* W1    = (const float*)d_in[9];
    const float* b1    = (const float*)d_in[10];
    const float* W2    = (const float*)d_in[11];
    const float* b2    = (const float*)d_in[12];

    const int B = in_sizes[0];
    const int ntiles = B / 256;

    cudaFuncSetAttribute(nnue_mma,
                         cudaFuncAttributeMaxDynamicSharedMemorySize, SMEM_BYTES);

    nnue_setup<<<26, 256>>>(Ww, Wb, W0, W1);
    nnue_mma<<<148, 256, SMEM_BYTES>>>(pov, white, black, bw, bb,
                                       b0, b1, W2, b2, (float*)d_out, ntiles);
}